// round 1
// baseline (speedup 1.0000x reference)
#include <cuda_runtime.h>
#include <cuda_bf16.h>

namespace {
constexpr int Tt  = 2048;   // sequence length
constexpr int Ee  = 1024;   // embed dim
constexpr int HD  = 64;     // head dim
constexpr int BM  = 64;     // query tile
constexpr int BN  = 64;     // key tile
constexpr int NTH = 256;
constexpr int NHtot = 64;   // N * H = 4 * 16
constexpr float SCALE = 0.125f;  // 64^-0.5
constexpr int ST = 68;      // smem row stride (floats): float4-aligned, low-conflict
}

// scratch: per-row softmax denominators (N*H*T floats = 2 MB)
__device__ float g_rowsum[NHtot * Tt];

// ---------------------------------------------------------------------------
// Kernel 1: E = exp(mask(Q K^T * scale)) written unnormalized to attn region,
//           row sums accumulated to g_rowsum, upper triangle zero-filled.
// ---------------------------------------------------------------------------
__global__ __launch_bounds__(NTH) void scores_kernel(
    const float* __restrict__ Q, const float* __restrict__ Kp,
    float* __restrict__ attn) {
  const int nh = blockIdx.y;
  const int n  = nh >> 4;
  const int h  = nh & 15;
  // largest q-tile first: heaviest blocks scheduled earliest (causal imbalance)
  const int q0 = ((int)gridDim.x - 1 - (int)blockIdx.x) * BM;
  const int tid = threadIdx.x;
  const int tx = tid & 15;
  const int ty = tid >> 4;

  __shared__ float sQT[HD][ST];   // [d][q_row]  (transposed for float4 reads)
  __shared__ float sKT[HD][ST];   // [d][k_row]

  const float* Qb = Q + ((size_t)(n * Tt + q0)) * Ee + h * HD;
  for (int idx = tid; idx < BM * HD; idx += NTH) {
    int r = idx >> 6, d = idx & 63;
    sQT[d][r] = Qb[(size_t)r * Ee + d];
  }

  float rsum[4] = {0.f, 0.f, 0.f, 0.f};
  float* ab = attn + ((size_t)nh * Tt + q0) * (size_t)Tt;
  const int kt_last = q0 >> 6;

  for (int kt = 0; kt <= kt_last; kt++) {
    const int k0 = kt * BN;
    __syncthreads();
    const float* Kb = Kp + ((size_t)(n * Tt + k0)) * Ee + h * HD;
    for (int idx = tid; idx < BN * HD; idx += NTH) {
      int r = idx >> 6, d = idx & 63;
      sKT[d][r] = Kb[(size_t)r * Ee + d];
    }
    __syncthreads();

    float acc[4][4];
#pragma unroll
    for (int i = 0; i < 4; i++)
#pragma unroll
      for (int j = 0; j < 4; j++) acc[i][j] = 0.f;

#pragma unroll 8
    for (int kk = 0; kk < HD; kk++) {
      float4 rq = *reinterpret_cast<const float4*>(&sQT[kk][ty * 4]);
      float4 rk = *reinterpret_cast<const float4*>(&sKT[kk][tx * 4]);
      const float* q4 = &rq.x;
      const float* k4 = &rk.x;
#pragma unroll
      for (int i = 0; i < 4; i++)
#pragma unroll
        for (int j = 0; j < 4; j++) acc[i][j] += q4[i] * k4[j];
    }

    const bool diag = (kt == kt_last);
#pragma unroll
    for (int i = 0; i < 4; i++) {
      const int q = q0 + ty * 4 + i;
      float4 out;
      float* o = &out.x;
#pragma unroll
      for (int j = 0; j < 4; j++) {
        const int k = k0 + tx * 4 + j;
        float e = __expf(acc[i][j] * SCALE);
        if (diag && k > q) e = 0.f;   // causal mask (softmax(-inf) == 0)
        o[j] = e;
        rsum[i] += e;
      }
      *reinterpret_cast<float4*>(ab + (size_t)(ty * 4 + i) * Tt + k0 + tx * 4) = out;
    }
  }

  // zero-fill fully-masked columns [q0+64, Tt) for every row of this tile
  {
    const int zs = q0 + BM;
    const int w4 = (Tt - zs) >> 2;
    const float4 z = make_float4(0.f, 0.f, 0.f, 0.f);
    for (int r = 0; r < BM; r++) {
      float4* row = reinterpret_cast<float4*>(ab + (size_t)r * Tt + zs);
      for (int c = tid; c < w4; c += NTH) row[c] = z;
    }
  }

  // reduce row sums across the 16 tx lanes (half-warp groups)
#pragma unroll
  for (int off = 8; off > 0; off >>= 1)
#pragma unroll
    for (int i = 0; i < 4; i++)
      rsum[i] += __shfl_down_sync(0xffffffffu, rsum[i], off, 16);
  if (tx == 0) {
#pragma unroll
    for (int i = 0; i < 4; i++)
      g_rowsum[nh * Tt + q0 + ty * 4 + i] = rsum[i];
  }
}

// ---------------------------------------------------------------------------
// Kernel 2: normalize P = E / l (in-place write), fused y = P @ V.
// ---------------------------------------------------------------------------
__global__ __launch_bounds__(NTH) void pv_kernel(
    const float* __restrict__ V, float* __restrict__ attn,
    float* __restrict__ Y) {
  const int nh = blockIdx.y;
  const int n  = nh >> 4;
  const int h  = nh & 15;
  const int q0 = ((int)gridDim.x - 1 - (int)blockIdx.x) * BM;
  const int tid = threadIdx.x;
  const int tx = tid & 15;
  const int ty = tid >> 4;

  __shared__ float sPT[BN][ST];   // [k][q_row] transposed
  __shared__ float sV[BN][ST];    // [k][d]
  __shared__ float sInv[BM];

  if (tid < BM) sInv[tid] = 1.f / g_rowsum[nh * Tt + q0 + tid];

  float acc[4][4];
#pragma unroll
  for (int i = 0; i < 4; i++)
#pragma unroll
    for (int j = 0; j < 4; j++) acc[i][j] = 0.f;

  float* ab = attn + ((size_t)nh * Tt + q0) * (size_t)Tt;
  const int kt_last = q0 >> 6;

  for (int kt = 0; kt <= kt_last; kt++) {
    const int k0 = kt * BN;
    __syncthreads();  // also orders sInv before first use

    // load E tile, normalize, write P back, stash transposed in smem
    for (int idx = tid; idx < BM * BN / 4; idx += NTH) {
      int r  = idx >> 4;
      int c4 = (idx & 15) * 4;
      float4 p = *reinterpret_cast<const float4*>(ab + (size_t)r * Tt + k0 + c4);
      const float inv = sInv[r];
      p.x *= inv; p.y *= inv; p.z *= inv; p.w *= inv;
      *reinterpret_cast<float4*>(ab + (size_t)r * Tt + k0 + c4) = p;
      sPT[c4 + 0][r] = p.x;
      sPT[c4 + 1][r] = p.y;
      sPT[c4 + 2][r] = p.z;
      sPT[c4 + 3][r] = p.w;
    }
    const float* Vb = V + ((size_t)(n * Tt + k0)) * Ee + h * HD;
    for (int idx = tid; idx < BN * HD; idx += NTH) {
      int r = idx >> 6, d = idx & 63;
      sV[r][d] = Vb[(size_t)r * Ee + d];
    }
    __syncthreads();

#pragma unroll 8
    for (int kk = 0; kk < BN; kk++) {
      float4 rp = *reinterpret_cast<const float4*>(&sPT[kk][ty * 4]);
      float4 rv = *reinterpret_cast<const float4*>(&sV[kk][tx * 4]);
      const float* p4 = &rp.x;
      const float* v4 = &rv.x;
#pragma unroll
      for (int i = 0; i < 4; i++)
#pragma unroll
        for (int j = 0; j < 4; j++) acc[i][j] += p4[i] * v4[j];
    }
  }

  float* Yb = Y + ((size_t)(n * Tt + q0)) * Ee + h * HD;
#pragma unroll
  for (int i = 0; i < 4; i++) {
    float4 o;
    o.x = acc[i][0]; o.y = acc[i][1]; o.z = acc[i][2]; o.w = acc[i][3];
    *reinterpret_cast<float4*>(Yb + (size_t)(ty * 4 + i) * Ee + tx * 4) = o;
  }
}

// ---------------------------------------------------------------------------
extern "C" void kernel_launch(void* const* d_in, const int* in_sizes, int n_in,
                              void* d_out, int out_size) {
  const float* q = (const float*)d_in[0];
  const float* k = (const float*)d_in[1];
  const float* v = (const float*)d_in[2];

  float* y    = (float*)d_out;                              // [4,2048,1024]
  float* attn = (float*)d_out + (size_t)4 * Tt * Ee;        // [4,16,2048,2048]

  dim3 grid(Tt / BM, NHtot);
  scores_kernel<<<grid, NTH>>>(q, k, attn);
  pv_kernel<<<grid, NTH>>>(v, attn, y);
}

// round 2
// speedup vs baseline: 1.2166x; 1.2166x over previous
#include <cuda_runtime.h>
#include <cuda_bf16.h>
#include <cstdint>

namespace {
constexpr int Tt  = 2048;
constexpr int Ee  = 1024;
constexpr int HD  = 64;
constexpr int BM1 = 128;   // scores q-tile
constexpr int BM2 = 64;    // pv q-tile
constexpr int BN  = 64;    // k tile
constexpr int NT1 = 256;
constexpr int NT2 = 128;
constexpr int NHtot = 64;
constexpr float SCALE = 0.125f;
constexpr int STB = 72;    // bf16 row stride: 144B rows, ldmatrix conflict-free
}

__device__ float g_rowsum[NHtot * Tt];

__device__ __forceinline__ uint32_t s2u(const void* p) {
  return (uint32_t)__cvta_generic_to_shared(p);
}
__device__ __forceinline__ void ldmx4(uint32_t* r, uint32_t a) {
  asm volatile("ldmatrix.sync.aligned.m8n8.x4.shared.b16 {%0,%1,%2,%3},[%4];"
               : "=r"(r[0]), "=r"(r[1]), "=r"(r[2]), "=r"(r[3]) : "r"(a));
}
__device__ __forceinline__ void ldmx4t(uint32_t* r, uint32_t a) {
  asm volatile("ldmatrix.sync.aligned.m8n8.x4.trans.shared.b16 {%0,%1,%2,%3},[%4];"
               : "=r"(r[0]), "=r"(r[1]), "=r"(r[2]), "=r"(r[3]) : "r"(a));
}
__device__ __forceinline__ void mmabf(float* c, const uint32_t* a, uint32_t b0, uint32_t b1) {
  asm volatile("mma.sync.aligned.m16n8k16.row.col.f32.bf16.bf16.f32 "
               "{%0,%1,%2,%3},{%4,%5,%6,%7},{%8,%9},{%0,%1,%2,%3};"
               : "+f"(c[0]), "+f"(c[1]), "+f"(c[2]), "+f"(c[3])
               : "r"(a[0]), "r"(a[1]), "r"(a[2]), "r"(a[3]), "r"(b0), "r"(b1));
}
__device__ __forceinline__ void cvt_hilo(float x, __nv_bfloat16& h, __nv_bfloat16& l) {
  h = __float2bfloat16(x);
  l = __float2bfloat16(x - __bfloat162float(h));
}

// ---------------------------------------------------------------------------
// Kernel 1: E = exp(mask(QK^T*scale)) unnormalized -> attn; rowsums -> global.
// bf16 split (3-term) tensor-core GEMM. BM1=128 rows, 8 warps x 16 rows.
// ---------------------------------------------------------------------------
__global__ __launch_bounds__(NT1) void scores_kernel(
    const float* __restrict__ Q, const float* __restrict__ Kp,
    float* __restrict__ attn) {
  const int nh = blockIdx.y, n = nh >> 4, h = nh & 15;
  const int q0 = ((int)gridDim.x - 1 - (int)blockIdx.x) * BM1;
  const int tid = threadIdx.x, warp = tid >> 5, lane = tid & 31;

  // one buffer: Q hi/lo first (freed into registers), then reused for K hi/lo
  __shared__ __nv_bfloat16 smem[2 * BM1 * STB];   // 36,864 B
  __nv_bfloat16* sQh = smem;
  __nv_bfloat16* sQl = smem + BM1 * STB;
  __nv_bfloat16* sKh = smem;
  __nv_bfloat16* sKl = smem + BN * STB;

  const float* Qb = Q + (size_t)(n * Tt + q0) * Ee + h * HD;
  for (int idx = tid; idx < BM1 * HD; idx += NT1) {
    int r = idx >> 6, d = idx & 63;
    cvt_hilo(Qb[(size_t)r * Ee + d], sQh[r * STB + d], sQl[r * STB + d]);
  }
  __syncthreads();

  // preload Q A-fragments (4 k-chunks of 16)
  uint32_t qah[4][4], qal[4][4];
  {
    const int ar = (warp << 4) + (lane & 15);
    const int ac = (lane >> 4) << 3;
#pragma unroll
    for (int ch = 0; ch < 4; ch++) {
      ldmx4(qah[ch], s2u(&sQh[ar * STB + ch * 16 + ac]));
      ldmx4(qal[ch], s2u(&sQl[ar * STB + ch * 16 + ac]));
    }
  }

  const int rowA = q0 + (warp << 4) + (lane >> 2);
  float* pRowA = attn + ((size_t)nh * Tt + rowA) * Tt;
  float* pRowB = pRowA + (size_t)8 * Tt;
  const int cOff = 2 * (lane & 3);
  float rs0 = 0.f, rs1 = 0.f;

  const int bN = ((lane >> 4) << 3) + (lane & 7);   // B matrix row (key token)
  const int bK = ((lane >> 3) & 1) << 3;            // B matrix col blk (d)
  const int kt_last = (q0 >> 6) + 1;

  for (int kt = 0; kt <= kt_last; kt++) {
    const int k0 = kt * BN;
    __syncthreads();
    const float* Kb = Kp + (size_t)(n * Tt + k0) * Ee + h * HD;
    for (int idx = tid; idx < BN * HD; idx += NT1) {
      int r = idx >> 6, d = idx & 63;
      cvt_hilo(Kb[(size_t)r * Ee + d], sKh[r * STB + d], sKl[r * STB + d]);
    }
    __syncthreads();

    float acc[8][4];
#pragma unroll
    for (int i = 0; i < 8; i++)
#pragma unroll
      for (int j = 0; j < 4; j++) acc[i][j] = 0.f;

#pragma unroll
    for (int ch = 0; ch < 4; ch++) {
#pragma unroll
      for (int p = 0; p < 4; p++) {
        uint32_t bh[4], bl[4];
        const int off = ((p << 4) + bN) * STB + (ch << 4) + bK;
        ldmx4(bh, s2u(&sKh[off]));
        ldmx4(bl, s2u(&sKl[off]));
        mmabf(acc[2 * p],     qah[ch], bh[0], bh[1]);
        mmabf(acc[2 * p],     qah[ch], bl[0], bl[1]);
        mmabf(acc[2 * p],     qal[ch], bh[0], bh[1]);
        mmabf(acc[2 * p + 1], qah[ch], bh[2], bh[3]);
        mmabf(acc[2 * p + 1], qah[ch], bl[2], bl[3]);
        mmabf(acc[2 * p + 1], qal[ch], bh[2], bh[3]);
      }
    }

    const bool msk = (k0 + BN - 1) > rowA;
#pragma unroll
    for (int nf = 0; nf < 8; nf++) {
      const int c = k0 + (nf << 3) + cOff;
      float e0 = __expf(acc[nf][0] * SCALE);
      float e1 = __expf(acc[nf][1] * SCALE);
      float e2 = __expf(acc[nf][2] * SCALE);
      float e3 = __expf(acc[nf][3] * SCALE);
      if (msk) {
        if (c     > rowA)     e0 = 0.f;
        if (c + 1 > rowA)     e1 = 0.f;
        if (c     > rowA + 8) e2 = 0.f;
        if (c + 1 > rowA + 8) e3 = 0.f;
      }
      rs0 += e0 + e1;
      rs1 += e2 + e3;
      *(float2*)(pRowA + c) = make_float2(e0, e1);
      *(float2*)(pRowB + c) = make_float2(e2, e3);
    }
  }

  // row sums: reduce over the 4 lanes sharing a row
  rs0 += __shfl_xor_sync(0xffffffffu, rs0, 1);
  rs0 += __shfl_xor_sync(0xffffffffu, rs0, 2);
  rs1 += __shfl_xor_sync(0xffffffffu, rs1, 1);
  rs1 += __shfl_xor_sync(0xffffffffu, rs1, 2);
  if ((lane & 3) == 0) {
    g_rowsum[nh * Tt + rowA]     = rs0;
    g_rowsum[nh * Tt + rowA + 8] = rs1;
  }

  // zero-fill fully-masked columns [q0+128, Tt)
  const int zs = q0 + BM1;
  if (zs < Tt) {
    const int w4 = (Tt - zs) >> 2;
    const float4 z = make_float4(0.f, 0.f, 0.f, 0.f);
    float* base = attn + ((size_t)nh * Tt + q0) * Tt + zs;
    for (int r = 0; r < BM1; r++) {
      float4* row = (float4*)(base + (size_t)r * Tt);
      for (int c = tid; c < w4; c += NT1) row[c] = z;
    }
  }
}

// ---------------------------------------------------------------------------
// Kernel 2: normalize P = E/l in place; y = P @ V via bf16-split tensor cores.
// BM2=64 rows, 4 warps x 16 rows.
// ---------------------------------------------------------------------------
__global__ __launch_bounds__(NT2) void pv_kernel(
    const float* __restrict__ V, float* __restrict__ attn,
    float* __restrict__ Y) {
  const int nh = blockIdx.y, n = nh >> 4, h = nh & 15;
  const int q0 = ((int)gridDim.x - 1 - (int)blockIdx.x) * BM2;
  const int tid = threadIdx.x, warp = tid >> 5, lane = tid & 31;

  __shared__ __nv_bfloat16 sPh[BM2 * STB], sPl[BM2 * STB];   // 18,432 B
  __shared__ __nv_bfloat16 sVh[BN * STB],  sVl[BN * STB];    // 18,432 B
  __shared__ float sInv[BM2];

  if (tid < BM2) sInv[tid] = 1.f / g_rowsum[nh * Tt + q0 + tid];

  float acc[8][4];
#pragma unroll
  for (int i = 0; i < 8; i++)
#pragma unroll
    for (int j = 0; j < 4; j++) acc[i][j] = 0.f;

  const int ar = (warp << 4) + (lane & 15);   // A (P) ldmatrix row
  const int ac = (lane >> 4) << 3;
  const int vk = (((lane >> 3) & 1) << 3) + (lane & 7);  // B (V, trans) row = token
  const int vn = (lane >> 4) << 3;                       // col blk = d
  float* ab = attn + ((size_t)nh * Tt + q0) * Tt;
  const int kt_last = q0 >> 6;

  for (int kt = 0; kt <= kt_last; kt++) {
    const int k0 = kt * BN;
    __syncthreads();   // also orders sInv before first use

    // load E tile, normalize, write P back, stash hi/lo bf16 in smem
    for (int idx = tid; idx < BM2 * 16; idx += NT2) {
      const int r = idx >> 4, c4 = (idx & 15) << 2;
      float* g = ab + (size_t)r * Tt + k0 + c4;
      float4 p = *(float4*)g;
      const float inv = sInv[r];
      p.x *= inv; p.y *= inv; p.z *= inv; p.w *= inv;
      *(float4*)g = p;
      __nv_bfloat16 h0, l0, h1, l1, h2, l2, h3, l3;
      cvt_hilo(p.x, h0, l0); cvt_hilo(p.y, h1, l1);
      cvt_hilo(p.z, h2, l2); cvt_hilo(p.w, h3, l3);
      __nv_bfloat162* ph = (__nv_bfloat162*)&sPh[r * STB + c4];
      __nv_bfloat162* pl = (__nv_bfloat162*)&sPl[r * STB + c4];
      ph[0] = __halves2bfloat162(h0, h1);
      ph[1] = __halves2bfloat162(h2, h3);
      pl[0] = __halves2bfloat162(l0, l1);
      pl[1] = __halves2bfloat162(l2, l3);
    }
    const float* Vb = V + (size_t)(n * Tt + k0) * Ee + h * HD;
    for (int idx = tid; idx < BN * HD; idx += NT2) {
      int r = idx >> 6, d = idx & 63;
      cvt_hilo(Vb[(size_t)r * Ee + d], sVh[r * STB + d], sVl[r * STB + d]);
    }
    __syncthreads();

#pragma unroll
    for (int ch = 0; ch < 4; ch++) {
      uint32_t ah[4], al[4];
      ldmx4(ah, s2u(&sPh[ar * STB + ch * 16 + ac]));
      ldmx4(al, s2u(&sPl[ar * STB + ch * 16 + ac]));
#pragma unroll
      for (int p = 0; p < 4; p++) {
        uint32_t bh[4], bl[4];
        const int off = (ch * 16 + vk) * STB + p * 16 + vn;
        ldmx4t(bh, s2u(&sVh[off]));
        ldmx4t(bl, s2u(&sVl[off]));
        mmabf(acc[2 * p],     ah, bh[0], bh[1]);
        mmabf(acc[2 * p],     ah, bl[0], bl[1]);
        mmabf(acc[2 * p],     al, bh[0], bh[1]);
        mmabf(acc[2 * p + 1], ah, bh[2], bh[3]);
        mmabf(acc[2 * p + 1], ah, bl[2], bl[3]);
        mmabf(acc[2 * p + 1], al, bh[2], bh[3]);
      }
    }
  }

  const int rowA = q0 + (warp << 4) + (lane >> 2);
  float* y0 = Y + (size_t)(n * Tt + rowA) * Ee + h * HD;
  float* y1 = y0 + (size_t)8 * Ee;
  const int cOff = 2 * (lane & 3);
#pragma unroll
  for (int nf = 0; nf < 8; nf++) {
    const int c = (nf << 3) + cOff;
    *(float2*)(y0 + c) = make_float2(acc[nf][0], acc[nf][1]);
    *(float2*)(y1 + c) = make_float2(acc[nf][2], acc[nf][3]);
  }
}

// ---------------------------------------------------------------------------
extern "C" void kernel_launch(void* const* d_in, const int* in_sizes, int n_in,
                              void* d_out, int out_size) {
  const float* q = (const float*)d_in[0];
  const float* k = (const float*)d_in[1];
  const float* v = (const float*)d_in[2];

  float* y    = (float*)d_out;                        // [4,2048,1024]
  float* attn = (float*)d_out + (size_t)4 * Tt * Ee;  // [4,16,2048,2048]

  dim3 g1(Tt / BM1, NHtot);
  dim3 g2(Tt / BM2, NHtot);
  scores_kernel<<<g1, NT1>>>(q, k, attn);
  pv_kernel<<<g2, NT2>>>(v, attn, y);
}

// round 3
// speedup vs baseline: 2.1290x; 1.7500x over previous
#include <cuda_runtime.h>
#include <cuda_bf16.h>
#include <cstdint>

namespace {
constexpr int Tt  = 2048;
constexpr int Ee  = 1024;
constexpr int HD  = 64;
constexpr int BM  = 64;     // q rows per block
constexpr int BN  = 64;     // k tile
constexpr int NT  = 128;    // 4 warps
constexpr int NHtot = 64;   // N*H
constexpr float SCALE = 0.125f;
constexpr int STB = 72;     // bf16 smem row stride (144B), ldmatrix conflict-free
// dynamic smem layout (bytes)
constexpr int OFF_KH  = 0;
constexpr int OFF_KL  = OFF_KH + BM * STB * 2;
constexpr int OFF_VH  = OFF_KL + BM * STB * 2;   // also Q hi during prologue
constexpr int OFF_VL  = OFF_VH + BM * STB * 2;   // also Q lo
constexpr int OFF_RAW = OFF_VL + BM * STB * 2;   // 16B-aligned (36864)
constexpr int SMEM_BYTES = OFF_RAW + BN * HD * 4;  // 53248
}

__device__ __forceinline__ uint32_t s2u(const void* p) {
  return (uint32_t)__cvta_generic_to_shared(p);
}
__device__ __forceinline__ void ldmx4(uint32_t* r, uint32_t a) {
  asm volatile("ldmatrix.sync.aligned.m8n8.x4.shared.b16 {%0,%1,%2,%3},[%4];"
               : "=r"(r[0]), "=r"(r[1]), "=r"(r[2]), "=r"(r[3]) : "r"(a));
}
__device__ __forceinline__ void ldmx4t(uint32_t* r, uint32_t a) {
  asm volatile("ldmatrix.sync.aligned.m8n8.x4.trans.shared.b16 {%0,%1,%2,%3},[%4];"
               : "=r"(r[0]), "=r"(r[1]), "=r"(r[2]), "=r"(r[3]) : "r"(a));
}
__device__ __forceinline__ void mmabf(float* c, const uint32_t* a, uint32_t b0, uint32_t b1) {
  asm volatile("mma.sync.aligned.m16n8k16.row.col.f32.bf16.bf16.f32 "
               "{%0,%1,%2,%3},{%4,%5,%6,%7},{%8,%9},{%0,%1,%2,%3};"
               : "+f"(c[0]), "+f"(c[1]), "+f"(c[2]), "+f"(c[3])
               : "r"(a[0]), "r"(a[1]), "r"(a[2]), "r"(a[3]), "r"(b0), "r"(b1));
}
// pack two fp32 -> bf16x2 (lo half = first arg)
__device__ __forceinline__ uint32_t pack2(float lo, float hi) {
  uint32_t r;
  asm("cvt.rn.bf16x2.f32 %0, %1, %2;" : "=r"(r) : "f"(hi), "f"(lo));
  return r;
}
__device__ __forceinline__ float bflo(uint32_t p) { return __uint_as_float(p << 16); }
__device__ __forceinline__ float bfhi(uint32_t p) { return __uint_as_float(p & 0xffff0000u); }

__device__ __forceinline__ void cpasync16(uint32_t saddr, const void* g) {
  asm volatile("cp.async.cg.shared.global [%0], [%1], 16;" :: "r"(saddr), "l"(g));
}

// split one float4 into hi/lo bf16x2 pairs and store (8B each)
__device__ __forceinline__ void store_hilo4(float4 f, __nv_bfloat16* ph, __nv_bfloat16* pl) {
  uint32_t h0 = pack2(f.x, f.y);
  uint32_t h1 = pack2(f.z, f.w);
  uint32_t l0 = pack2(f.x - bflo(h0), f.y - bfhi(h0));
  uint32_t l1 = pack2(f.z - bflo(h1), f.w - bfhi(h1));
  *reinterpret_cast<uint2*>(ph) = make_uint2(h0, h1);
  *reinterpret_cast<uint2*>(pl) = make_uint2(l0, l1);
}

__device__ __forceinline__ void ldg_tile(const float* g, float4* st, int tid) {
#pragma unroll
  for (int i = 0; i < 8; i++) {
    int idx = tid + i * NT;
    st[i] = *reinterpret_cast<const float4*>(g + (size_t)(idx >> 4) * Ee + ((idx & 15) << 2));
  }
}
__device__ __forceinline__ void sts_hilo(const float4* st, __nv_bfloat16* sh,
                                         __nv_bfloat16* sl, int tid) {
#pragma unroll
  for (int i = 0; i < 8; i++) {
    int idx = tid + i * NT;
    int r = idx >> 4, c4 = (idx & 15) << 2;
    store_hilo4(st[i], &sh[r * STB + c4], &sl[r * STB + c4]);
  }
}

// ---------------------------------------------------------------------------
// Fused causal attention: pass1 recomputes rowsums, pass2 writes normalized
// attn + accumulates y = P@V. All GEMMs bf16 split-precision (3-term).
// ---------------------------------------------------------------------------
__global__ __launch_bounds__(NT, 3) void fused_attn_kernel(
    const float* __restrict__ Q, const float* __restrict__ Kg,
    const float* __restrict__ Vg, float* __restrict__ attn,
    float* __restrict__ Y) {
  extern __shared__ char smem[];
  __nv_bfloat16* sKh = (__nv_bfloat16*)(smem + OFF_KH);
  __nv_bfloat16* sKl = (__nv_bfloat16*)(smem + OFF_KL);
  __nv_bfloat16* sVh = (__nv_bfloat16*)(smem + OFF_VH);  // Q hi in prologue
  __nv_bfloat16* sVl = (__nv_bfloat16*)(smem + OFF_VL);  // Q lo in prologue
  float4* rawV = (float4*)(smem + OFF_RAW);
  const uint32_t rawVaddr = s2u(rawV);

  const int nh = blockIdx.y, n = nh >> 4, h = nh & 15;
  const int q0 = ((int)gridDim.x - 1 - (int)blockIdx.x) * BM;  // heavy-first
  const int tid = threadIdx.x, warp = tid >> 5, lane = tid & 31;
  const int ktl = q0 >> 6;

  const float* Qb = Q + (size_t)(n * Tt + q0) * Ee + h * HD;
  const float* Kbase = Kg + (size_t)(n * Tt) * Ee + h * HD;
  const float* Vbase = Vg + (size_t)(n * Tt) * Ee + h * HD;

  // ---- prologue: Q -> smem (hi/lo) -> register fragments ----
  {
    float4 qst[8];
    ldg_tile(Qb, qst, tid);
    sts_hilo(qst, sVh, sVl, tid);
  }
  __syncthreads();
  uint32_t qah[4][4], qal[4][4];
  {
    const int ar = (warp << 4) + (lane & 15);
    const int ac = (lane >> 4) << 3;
#pragma unroll
    for (int ch = 0; ch < 4; ch++) {
      ldmx4(qah[ch], s2u(&sVh[ar * STB + ch * 16 + ac]));
      ldmx4(qal[ch], s2u(&sVl[ar * STB + ch * 16 + ac]));
    }
  }

  const int rowA = q0 + (warp << 4) + (lane >> 2);
  const int bN = ((lane >> 4) << 3) + (lane & 7);
  const int bK = ((lane >> 3) & 1) << 3;
  const int cOff = 2 * (lane & 3);

  // ================= pass 1: row sums =================
  float4 kst[8];
  ldg_tile(Kbase, kst, tid);
  float rs0 = 0.f, rs1 = 0.f;

  for (int kt = 0; kt <= ktl; kt++) {
    const int k0 = kt * BN;
    __syncthreads();                 // smem K writable (prev mma / Q-frag reads done)
    sts_hilo(kst, sKh, sKl, tid);
    __syncthreads();
    if (kt < ktl) ldg_tile(Kbase + (size_t)(kt + 1) * BN * Ee, kst, tid);

    float sacc[8][4];
#pragma unroll
    for (int i = 0; i < 8; i++)
#pragma unroll
      for (int j = 0; j < 4; j++) sacc[i][j] = 0.f;

#pragma unroll
    for (int ch = 0; ch < 4; ch++)
#pragma unroll
      for (int p = 0; p < 4; p++) {
        uint32_t bh[4], bl[4];
        const int off = ((p << 4) + bN) * STB + (ch << 4) + bK;
        ldmx4(bh, s2u(&sKh[off]));
        ldmx4(bl, s2u(&sKl[off]));
        mmabf(sacc[2 * p],     qah[ch], bh[0], bh[1]);
        mmabf(sacc[2 * p],     qah[ch], bl[0], bl[1]);
        mmabf(sacc[2 * p],     qal[ch], bh[0], bh[1]);
        mmabf(sacc[2 * p + 1], qah[ch], bh[2], bh[3]);
        mmabf(sacc[2 * p + 1], qah[ch], bl[2], bl[3]);
        mmabf(sacc[2 * p + 1], qal[ch], bh[2], bh[3]);
      }

    const bool msk = (k0 + BN - 1) > rowA;
#pragma unroll
    for (int nf = 0; nf < 8; nf++) {
      const int c = k0 + (nf << 3) + cOff;
      float e0 = __expf(sacc[nf][0] * SCALE);
      float e1 = __expf(sacc[nf][1] * SCALE);
      float e2 = __expf(sacc[nf][2] * SCALE);
      float e3 = __expf(sacc[nf][3] * SCALE);
      if (msk) {
        if (c     > rowA)     e0 = 0.f;
        if (c + 1 > rowA)     e1 = 0.f;
        if (c     > rowA + 8) e2 = 0.f;
        if (c + 1 > rowA + 8) e3 = 0.f;
      }
      rs0 += e0 + e1;
      rs1 += e2 + e3;
    }
  }
  rs0 += __shfl_xor_sync(0xffffffffu, rs0, 1);
  rs0 += __shfl_xor_sync(0xffffffffu, rs0, 2);
  rs1 += __shfl_xor_sync(0xffffffffu, rs1, 1);
  rs1 += __shfl_xor_sync(0xffffffffu, rs1, 2);
  const float inv0 = 1.f / rs0;
  const float inv1 = 1.f / rs1;

  // ---- zero-fill fully-masked columns [q0+64, Tt) (overlaps with pass 2) ----
  if (q0 + BM < Tt) {
    const int zs = q0 + BM;
    const int w4 = (Tt - zs) >> 2;
    const float4 z = make_float4(0.f, 0.f, 0.f, 0.f);
    float* base = attn + ((size_t)nh * Tt + q0) * Tt + zs;
    for (int r = 0; r < BM; r++) {
      float4* row = (float4*)(base + (size_t)r * Tt);
      for (int c = tid; c < w4; c += NT) row[c] = z;
    }
  }

  // ================= pass 2: attn write + P@V =================
  ldg_tile(Kbase, kst, tid);
  float yacc[8][4];
#pragma unroll
  for (int i = 0; i < 8; i++)
#pragma unroll
    for (int j = 0; j < 4; j++) yacc[i][j] = 0.f;

  const int vk = (((lane >> 3) & 1) << 3) + (lane & 7);
  const int vn = (lane >> 4) << 3;
  float* pRowA = attn + ((size_t)nh * Tt + rowA) * Tt;
  float* pRowB = pRowA + (size_t)8 * Tt;

  for (int kt = 0; kt <= ktl; kt++) {
    const int k0 = kt * BN;
    __syncthreads();                 // K/V smem + rawV writable
    sts_hilo(kst, sKh, sKl, tid);
    {  // async V tile -> raw staging (fp32)
      const float* Vb = Vbase + (size_t)k0 * Ee;
#pragma unroll
      for (int i = 0; i < 8; i++) {
        int idx = tid + i * NT;
        cpasync16(rawVaddr + idx * 16,
                  Vb + (size_t)(idx >> 4) * Ee + ((idx & 15) << 2));
      }
      asm volatile("cp.async.commit_group;");
    }
    __syncthreads();                 // K hi/lo visible
    if (kt < ktl) ldg_tile(Kbase + (size_t)(kt + 1) * BN * Ee, kst, tid);

    float sacc[8][4];
#pragma unroll
    for (int i = 0; i < 8; i++)
#pragma unroll
      for (int j = 0; j < 4; j++) sacc[i][j] = 0.f;

#pragma unroll
    for (int ch = 0; ch < 4; ch++)
#pragma unroll
      for (int p = 0; p < 4; p++) {
        uint32_t bh[4], bl[4];
        const int off = ((p << 4) + bN) * STB + (ch << 4) + bK;
        ldmx4(bh, s2u(&sKh[off]));
        ldmx4(bl, s2u(&sKl[off]));
        mmabf(sacc[2 * p],     qah[ch], bh[0], bh[1]);
        mmabf(sacc[2 * p],     qah[ch], bl[0], bl[1]);
        mmabf(sacc[2 * p],     qal[ch], bh[0], bh[1]);
        mmabf(sacc[2 * p + 1], qah[ch], bh[2], bh[3]);
        mmabf(sacc[2 * p + 1], qah[ch], bl[2], bl[3]);
        mmabf(sacc[2 * p + 1], qal[ch], bh[2], bh[3]);
      }

    // exp, normalize, store attn; keep P in sacc
    const bool msk = (k0 + BN - 1) > rowA;
#pragma unroll
    for (int nf = 0; nf < 8; nf++) {
      const int c = k0 + (nf << 3) + cOff;
      float e0 = __expf(sacc[nf][0] * SCALE) * inv0;
      float e1 = __expf(sacc[nf][1] * SCALE) * inv0;
      float e2 = __expf(sacc[nf][2] * SCALE) * inv1;
      float e3 = __expf(sacc[nf][3] * SCALE) * inv1;
      if (msk) {
        if (c     > rowA)     e0 = 0.f;
        if (c + 1 > rowA)     e1 = 0.f;
        if (c     > rowA + 8) e2 = 0.f;
        if (c + 1 > rowA + 8) e3 = 0.f;
      }
      *(float2*)(pRowA + c) = make_float2(e0, e1);
      *(float2*)(pRowB + c) = make_float2(e2, e3);
      sacc[nf][0] = e0; sacc[nf][1] = e1; sacc[nf][2] = e2; sacc[nf][3] = e3;
    }

    // V: raw fp32 -> hi/lo bf16 smem
    asm volatile("cp.async.wait_group 0;");
#pragma unroll
    for (int i = 0; i < 8; i++) {
      int idx = tid + i * NT;
      int r = idx >> 4, c4 = (idx & 15) << 2;
      store_hilo4(rawV[idx], &sVh[r * STB + c4], &sVl[r * STB + c4]);
    }
    __syncthreads();                 // V hi/lo visible

    // P@V: build A-fragments from sacc registers (C-layout == A-layout)
#pragma unroll
    for (int cc = 0; cc < 4; cc++) {
      uint32_t ah[4], al[4];
      ah[0] = pack2(sacc[2 * cc][0],     sacc[2 * cc][1]);
      ah[1] = pack2(sacc[2 * cc][2],     sacc[2 * cc][3]);
      ah[2] = pack2(sacc[2 * cc + 1][0], sacc[2 * cc + 1][1]);
      ah[3] = pack2(sacc[2 * cc + 1][2], sacc[2 * cc + 1][3]);
      al[0] = pack2(sacc[2 * cc][0] - bflo(ah[0]),     sacc[2 * cc][1] - bfhi(ah[0]));
      al[1] = pack2(sacc[2 * cc][2] - bflo(ah[1]),     sacc[2 * cc][3] - bfhi(ah[1]));
      al[2] = pack2(sacc[2 * cc + 1][0] - bflo(ah[2]), sacc[2 * cc + 1][1] - bfhi(ah[2]));
      al[3] = pack2(sacc[2 * cc + 1][2] - bflo(ah[3]), sacc[2 * cc + 1][3] - bfhi(ah[3]));
#pragma unroll
      for (int p = 0; p < 4; p++) {
        uint32_t bh[4], bl[4];
        const int off = (cc * 16 + vk) * STB + p * 16 + vn;
        ldmx4t(bh, s2u(&sVh[off]));
        ldmx4t(bl, s2u(&sVl[off]));
        mmabf(yacc[2 * p],     ah, bh[0], bh[1]);
        mmabf(yacc[2 * p],     ah, bl[0], bl[1]);
        mmabf(yacc[2 * p],     al, bh[0], bh[1]);
        mmabf(yacc[2 * p + 1], ah, bh[2], bh[3]);
        mmabf(yacc[2 * p + 1], ah, bl[2], bl[3]);
        mmabf(yacc[2 * p + 1], al, bh[2], bh[3]);
      }
    }
  }

  // ---- y store ----
  float* y0 = Y + (size_t)(n * Tt + rowA) * Ee + h * HD;
  float* y1 = y0 + (size_t)8 * Ee;
#pragma unroll
  for (int nf = 0; nf < 8; nf++) {
    const int c = (nf << 3) + cOff;
    *(float2*)(y0 + c) = make_float2(yacc[nf][0], yacc[nf][1]);
    *(float2*)(y1 + c) = make_float2(yacc[nf][2], yacc[nf][3]);
  }
}

// ---------------------------------------------------------------------------
extern "C" void kernel_launch(void* const* d_in, const int* in_sizes, int n_in,
                              void* d_out, int out_size) {
  const float* q = (const float*)d_in[0];
  const float* k = (const float*)d_in[1];
  const float* v = (const float*)d_in[2];

  float* y    = (float*)d_out;
  float* attn = (float*)d_out + (size_t)4 * Tt * Ee;

  cudaFuncSetAttribute(fused_attn_kernel,
                       cudaFuncAttributeMaxDynamicSharedMemorySize, SMEM_BYTES);
  dim3 grid(Tt / BM, NHtot);
  fused_attn_kernel<<<grid, NT, SMEM_BYTES>>>(q, k, v, attn, y);
}

// round 4
// speedup vs baseline: 2.3745x; 1.1153x over previous
#include <cuda_runtime.h>
#include <cuda_bf16.h>
#include <cstdint>

namespace {
constexpr int Tt  = 2048;
constexpr int Ee  = 1024;
constexpr int HD  = 64;
constexpr int BM  = 64;
constexpr int BN  = 64;
constexpr int NT  = 128;
constexpr int NHtot = 64;
constexpr float SCALE = 0.125f;
constexpr int PLANE = 8192;           // one plane (64 tok x 128B), swizzled
constexpr int STAGE = 2 * PLANE;      // hi + lo
constexpr int SMEM_BYTES = 4 * STAGE; // K0,K1,V0,V1 = 65536
}

// preconverted per-head bf16 hi/lo planes: [nh][t][d]
__device__ __align__(128) __nv_bfloat16 gQh[(size_t)NHtot * Tt * HD];
__device__ __align__(128) __nv_bfloat16 gQl[(size_t)NHtot * Tt * HD];
__device__ __align__(128) __nv_bfloat16 gKh[(size_t)NHtot * Tt * HD];
__device__ __align__(128) __nv_bfloat16 gKl[(size_t)NHtot * Tt * HD];
__device__ __align__(128) __nv_bfloat16 gVh[(size_t)NHtot * Tt * HD];
__device__ __align__(128) __nv_bfloat16 gVl[(size_t)NHtot * Tt * HD];

__device__ __forceinline__ uint32_t s2u(const void* p) {
  return (uint32_t)__cvta_generic_to_shared(p);
}
__device__ __forceinline__ void ldmx4(uint32_t* r, uint32_t a) {
  asm volatile("ldmatrix.sync.aligned.m8n8.x4.shared.b16 {%0,%1,%2,%3},[%4];"
               : "=r"(r[0]), "=r"(r[1]), "=r"(r[2]), "=r"(r[3]) : "r"(a));
}
__device__ __forceinline__ void ldmx4t(uint32_t* r, uint32_t a) {
  asm volatile("ldmatrix.sync.aligned.m8n8.x4.trans.shared.b16 {%0,%1,%2,%3},[%4];"
               : "=r"(r[0]), "=r"(r[1]), "=r"(r[2]), "=r"(r[3]) : "r"(a));
}
__device__ __forceinline__ void mmabf(float* c, const uint32_t* a, uint32_t b0, uint32_t b1) {
  asm volatile("mma.sync.aligned.m16n8k16.row.col.f32.bf16.bf16.f32 "
               "{%0,%1,%2,%3},{%4,%5,%6,%7},{%8,%9},{%0,%1,%2,%3};"
               : "+f"(c[0]), "+f"(c[1]), "+f"(c[2]), "+f"(c[3])
               : "r"(a[0]), "r"(a[1]), "r"(a[2]), "r"(a[3]), "r"(b0), "r"(b1));
}
__device__ __forceinline__ uint32_t pack2(float lo, float hi) {
  uint32_t r;
  asm("cvt.rn.bf16x2.f32 %0, %1, %2;" : "=r"(r) : "f"(hi), "f"(lo));
  return r;
}
__device__ __forceinline__ float bflo(uint32_t p) { return __uint_as_float(p << 16); }
__device__ __forceinline__ float bfhi(uint32_t p) { return __uint_as_float(p & 0xffff0000u); }
__device__ __forceinline__ void cpasync16(uint32_t saddr, const void* g) {
  asm volatile("cp.async.cg.shared.global [%0], [%1], 16;" :: "r"(saddr), "l"(g));
}
__device__ __forceinline__ void cp_commit() { asm volatile("cp.async.commit_group;"); }

// issue one 64-token hi/lo tile into a swizzled smem stage (8 cp.async/thread)
__device__ __forceinline__ void issue_tile(const __nv_bfloat16* ph,
                                           const __nv_bfloat16* pl,
                                           uint32_t dst, int tid) {
#pragma unroll
  for (int i = 0; i < 4; i++) {
    int q = tid + i * NT;             // 0..511 chunk id
    int r = q >> 3, c = q & 7;
    uint32_t off = r * 128 + (((c ^ (r & 7))) << 4);
    const char* src = (const char*)ph + r * 128 + c * 16;
    const char* srl = (const char*)pl + r * 128 + c * 16;
    cpasync16(dst + off, src);
    cpasync16(dst + PLANE + off, srl);
  }
}

// QK tile: sacc += Q(frag) * K(stage)^T, 3-term bf16 split
__device__ __forceinline__ void qk_mma(float sacc[8][4], uint32_t Kst,
                                       const uint32_t qah[4][4],
                                       const uint32_t qal[4][4], int lane) {
  const int bTok = ((lane >> 4) << 3) + (lane & 7);
  const int bSel = (lane >> 3) & 1;
  const int x7 = lane & 7;
#pragma unroll
  for (int ch = 0; ch < 4; ch++) {
#pragma unroll
    for (int p = 0; p < 4; p++) {
      uint32_t bh[4], bl[4];
      uint32_t a = Kst + (p * 16 + bTok) * 128 + (((2 * ch + bSel) ^ x7) << 4);
      ldmx4(bh, a);
      ldmx4(bl, a + PLANE);
      mmabf(sacc[2 * p],     qah[ch], bh[0], bh[1]);
      mmabf(sacc[2 * p],     qah[ch], bl[0], bl[1]);
      mmabf(sacc[2 * p],     qal[ch], bh[0], bh[1]);
      mmabf(sacc[2 * p + 1], qah[ch], bh[2], bh[3]);
      mmabf(sacc[2 * p + 1], qah[ch], bl[2], bl[3]);
      mmabf(sacc[2 * p + 1], qal[ch], bh[2], bh[3]);
    }
  }
}

// ---------------------------------------------------------------------------
// pre-pass: fp32 [n][t][e] -> per-head bf16 hi/lo planes [nh][t][d]
// ---------------------------------------------------------------------------
__global__ __launch_bounds__(256) void conv_kernel(
    const float* __restrict__ Q, const float* __restrict__ K,
    const float* __restrict__ V) {
  const float* src;
  __nv_bfloat16 *dh, *dl;
  if (blockIdx.y == 0)      { src = Q; dh = gQh; dl = gQl; }
  else if (blockIdx.y == 1) { src = K; dh = gKh; dl = gKl; }
  else                      { src = V; dh = gVh; dl = gVl; }
  size_t i = (size_t)blockIdx.x * 256 + threadIdx.x;   // over 4*2048*512 float2
  float2 f = ((const float2*)src)[i];
  int e2 = (int)(i & 511);
  size_t tn = i >> 9;                       // n*2048 + t
  int e = e2 << 1, h = e >> 6, d = e & 63;
  int t = (int)(tn & 2047), n = (int)(tn >> 11);
  size_t o = ((((size_t)(n * 16 + h)) * Tt + t) * HD + d) >> 1;
  uint32_t hi = pack2(f.x, f.y);
  uint32_t lo = pack2(f.x - bflo(hi), f.y - bfhi(hi));
  ((uint32_t*)dh)[o] = hi;
  ((uint32_t*)dl)[o] = lo;
}

// ---------------------------------------------------------------------------
// fused attention
// ---------------------------------------------------------------------------
__global__ __launch_bounds__(NT, 3) void fused_attn_kernel(
    float* __restrict__ attn, float* __restrict__ Y) {
  extern __shared__ char smem[];
  const uint32_t sb = s2u(smem);
  const uint32_t S4[4] = {sb, sb + STAGE, sb + 2 * STAGE, sb + 3 * STAGE};

  const int nh = blockIdx.y, n = nh >> 4;
  const int q0 = ((int)gridDim.x - 1 - (int)blockIdx.x) * BM;
  const int tid = threadIdx.x, warp = tid >> 5, lane = tid & 31;
  const int ktl = q0 >> 6;

  const size_t hb = (size_t)nh * Tt * HD;
  const __nv_bfloat16 *Qh = gQh + hb + (size_t)q0 * HD, *Ql = gQl + hb + (size_t)q0 * HD;
  const __nv_bfloat16 *Kh = gKh + hb, *Kl = gKl + hb;
  const __nv_bfloat16 *Vh = gVh + hb, *Vl = gVl + hb;

  // ---- prologue: Q -> V0 stage -> register fragments ----
  issue_tile(Qh, Ql, S4[2], tid);
  cp_commit();
  asm volatile("cp.async.wait_group 0;");
  __syncthreads();
  uint32_t qah[4][4], qal[4][4];
  {
    const int ar = (warp << 4) + (lane & 15);
    const int aSel = lane >> 4;
    const int x7a = ar & 7;
#pragma unroll
    for (int ch = 0; ch < 4; ch++) {
      uint32_t a = S4[2] + ar * 128 + (((2 * ch + aSel) ^ x7a) << 4);
      ldmx4(qah[ch], a);
      ldmx4(qal[ch], a + PLANE);
    }
  }
  __syncthreads();   // all warps done reading Q stage before pass-1 reuses it

  const int rowA = q0 + (warp << 4) + (lane >> 2);
  const int cOff = 2 * (lane & 3);

  // ================= pass 1: row sums (4-stage K pipeline) =================
  float rs0 = 0.f, rs1 = 0.f;
#pragma unroll
  for (int t = 0; t < 3; t++) {   // prologue: tiles 0..2 (clamped)
    int tt = t <= ktl ? t : ktl;
    issue_tile(Kh + (size_t)tt * BN * HD, Kl + (size_t)tt * BN * HD, S4[t & 3], tid);
    cp_commit();
  }
  for (int kt = 0; kt <= ktl; kt++) {
    asm volatile("cp.async.wait_group 2;");
    __syncthreads();
    {
      int tt = kt + 3 <= ktl ? kt + 3 : ktl;
      issue_tile(Kh + (size_t)tt * BN * HD, Kl + (size_t)tt * BN * HD, S4[(kt + 3) & 3], tid);
      cp_commit();
    }
    float sacc[8][4];
#pragma unroll
    for (int i = 0; i < 8; i++)
#pragma unroll
      for (int j = 0; j < 4; j++) sacc[i][j] = 0.f;
    qk_mma(sacc, S4[kt & 3], qah, qal, lane);

    const int k0 = kt * BN;
    const bool msk = (k0 + BN - 1) > rowA;
#pragma unroll
    for (int nf = 0; nf < 8; nf++) {
      const int c = k0 + (nf << 3) + cOff;
      float e0 = __expf(sacc[nf][0] * SCALE);
      float e1 = __expf(sacc[nf][1] * SCALE);
      float e2 = __expf(sacc[nf][2] * SCALE);
      float e3 = __expf(sacc[nf][3] * SCALE);
      if (msk) {
        if (c     > rowA)     e0 = 0.f;
        if (c + 1 > rowA)     e1 = 0.f;
        if (c     > rowA + 8) e2 = 0.f;
        if (c + 1 > rowA + 8) e3 = 0.f;
      }
      rs0 += e0 + e1;
      rs1 += e2 + e3;
    }
  }
  rs0 += __shfl_xor_sync(0xffffffffu, rs0, 1);
  rs0 += __shfl_xor_sync(0xffffffffu, rs0, 2);
  rs1 += __shfl_xor_sync(0xffffffffu, rs1, 1);
  rs1 += __shfl_xor_sync(0xffffffffu, rs1, 2);
  const float inv0 = 1.f / rs0;
  const float inv1 = 1.f / rs1;

  // ================= pass 2: attn write + P@V (2x2 stage pipeline) =========
  __syncthreads();   // pass-1 smem reads done everywhere
  issue_tile(Kh, Kl, S4[0], tid);
  issue_tile(Vh, Vl, S4[2], tid);
  cp_commit();

  // zero-fill fully-masked columns (overlaps the first loads)
  if (q0 + BM < Tt) {
    const int zs = q0 + BM;
    const int w4 = (Tt - zs) >> 2;
    const float4 z = make_float4(0.f, 0.f, 0.f, 0.f);
    float* base = attn + ((size_t)nh * Tt + q0) * Tt + zs;
    for (int r = 0; r < BM; r++) {
      float4* row = (float4*)(base + (size_t)r * Tt);
      for (int c = tid; c < w4; c += NT) row[c] = z;
    }
  }

  float yacc[8][4];
#pragma unroll
  for (int i = 0; i < 8; i++)
#pragma unroll
    for (int j = 0; j < 4; j++) yacc[i][j] = 0.f;

  const int vTok = (((lane >> 3) & 1) << 3) + (lane & 7);
  const int vSel = lane >> 4;
  const int x7 = lane & 7;
  float* pRowA = attn + ((size_t)nh * Tt + rowA) * Tt;
  float* pRowB = pRowA + (size_t)8 * Tt;

  for (int kt = 0; kt <= ktl; kt++) {
    asm volatile("cp.async.wait_group 0;");
    __syncthreads();
    if (kt < ktl) {
      issue_tile(Kh + (size_t)(kt + 1) * BN * HD, Kl + (size_t)(kt + 1) * BN * HD,
                 S4[(kt + 1) & 1], tid);
      issue_tile(Vh + (size_t)(kt + 1) * BN * HD, Vl + (size_t)(kt + 1) * BN * HD,
                 S4[2 + ((kt + 1) & 1)], tid);
      cp_commit();
    }
    const uint32_t Kst = S4[kt & 1];
    const uint32_t Vst = S4[2 + (kt & 1)];

    float sacc[8][4];
#pragma unroll
    for (int i = 0; i < 8; i++)
#pragma unroll
      for (int j = 0; j < 4; j++) sacc[i][j] = 0.f;
    qk_mma(sacc, Kst, qah, qal, lane);

    const int k0 = kt * BN;
    const bool msk = (k0 + BN - 1) > rowA;
#pragma unroll
    for (int cc = 0; cc < 4; cc++) {
      // exp + normalize + mask + store the two fragments of this k-chunk
      float e[2][4];
#pragma unroll
      for (int s = 0; s < 2; s++) {
        const int nf = 2 * cc + s;
        const int c = k0 + (nf << 3) + cOff;
        e[s][0] = __expf(sacc[nf][0] * SCALE) * inv0;
        e[s][1] = __expf(sacc[nf][1] * SCALE) * inv0;
        e[s][2] = __expf(sacc[nf][2] * SCALE) * inv1;
        e[s][3] = __expf(sacc[nf][3] * SCALE) * inv1;
        if (msk) {
          if (c     > rowA)     e[s][0] = 0.f;
          if (c + 1 > rowA)     e[s][1] = 0.f;
          if (c     > rowA + 8) e[s][2] = 0.f;
          if (c + 1 > rowA + 8) e[s][3] = 0.f;
        }
        *(float2*)(pRowA + c) = make_float2(e[s][0], e[s][1]);
        *(float2*)(pRowB + c) = make_float2(e[s][2], e[s][3]);
      }
      // pack P fragments (C-layout == A-layout) and run PV for this k-chunk
      uint32_t ah[4], al[4];
      ah[0] = pack2(e[0][0], e[0][1]);
      ah[1] = pack2(e[0][2], e[0][3]);
      ah[2] = pack2(e[1][0], e[1][1]);
      ah[3] = pack2(e[1][2], e[1][3]);
      al[0] = pack2(e[0][0] - bflo(ah[0]), e[0][1] - bfhi(ah[0]));
      al[1] = pack2(e[0][2] - bflo(ah[1]), e[0][3] - bfhi(ah[1]));
      al[2] = pack2(e[1][0] - bflo(ah[2]), e[1][1] - bfhi(ah[2]));
      al[3] = pack2(e[1][2] - bflo(ah[3]), e[1][3] - bfhi(ah[3]));
#pragma unroll
      for (int p = 0; p < 4; p++) {
        uint32_t bh[4], bl[4];
        uint32_t a = Vst + (cc * 16 + vTok) * 128 + (((2 * p + vSel) ^ x7) << 4);
        ldmx4t(bh, a);
        ldmx4t(bl, a + PLANE);
        mmabf(yacc[2 * p],     ah, bh[0], bh[1]);
        mmabf(yacc[2 * p],     ah, bl[0], bl[1]);
        mmabf(yacc[2 * p],     al, bh[0], bh[1]);
        mmabf(yacc[2 * p + 1], ah, bh[2], bh[3]);
        mmabf(yacc[2 * p + 1], ah, bl[2], bl[3]);
        mmabf(yacc[2 * p + 1], al, bh[2], bh[3]);
      }
    }
  }

  // ---- y store ----
  const int h = nh & 15;
  float* y0 = Y + (size_t)(n * Tt + rowA) * Ee + h * HD;
  float* y1 = y0 + (size_t)8 * Ee;
#pragma unroll
  for (int nf = 0; nf < 8; nf++) {
    const int c = (nf << 3) + cOff;
    *(float2*)(y0 + c) = make_float2(yacc[nf][0], yacc[nf][1]);
    *(float2*)(y1 + c) = make_float2(yacc[nf][2], yacc[nf][3]);
  }
}

// ---------------------------------------------------------------------------
extern "C" void kernel_launch(void* const* d_in, const int* in_sizes, int n_in,
                              void* d_out, int out_size) {
  const float* q = (const float*)d_in[0];
  const float* k = (const float*)d_in[1];
  const float* v = (const float*)d_in[2];

  float* y    = (float*)d_out;
  float* attn = (float*)d_out + (size_t)4 * Tt * Ee;

  dim3 cg((unsigned)((size_t)4 * Tt * (Ee / 2) / 256), 3);
  conv_kernel<<<cg, 256>>>(q, k, v);

  cudaFuncSetAttribute(fused_attn_kernel,
                       cudaFuncAttributeMaxDynamicSharedMemorySize, SMEM_BYTES);
  dim3 grid(Tt / BM, NHtot);
  fused_attn_kernel<<<grid, NT, SMEM_BYTES>>>(attn, y);
}